// round 16
// baseline (speedup 1.0000x reference)
#include <cuda_runtime.h>
#include <cuda_fp16.h>
#include <cuda_bf16.h>
#include <cstdint>

// ---------------- problem constants ----------------
#define NPTS 20000
#define NPAD 20096          // 157*128
#define MNBR 20
#define ERBF 20
#define HDIM 128
#define BCRY 200
#define NBLK 8
#define PI_F 3.14159265358979f
#define KNOT 4096
#define DMAX_CHE 8.81f
#define DMAX_VDW 13.21f
#define CH (128 * 72)       // shorts per plane per k-chunk

typedef unsigned long long u64;

// ---------------- device scratch ----------------
__device__ int   g_order;
__device__ float g_nodesA[NPTS * HDIM];
__device__ float g_nodesB[NPTS * HDIM];
__device__ __half2 g_STh[(size_t)NPTS * 512];            // [S_che|T_che|S_vdw|T_vdw] x 128 half2 (filt,core)
__device__ float g_We[3 * 2 * ERBF * 256];
__device__ float g_be[3 * 2 * 256];
__device__ uint2 g_tab16[(size_t)3 * 2 * KNOT * 128];    // packed fp16: {f_j,c_j,f_j+1,c_j+1} per (j,h)
// bf16 split operands for tensor-core GEMM (tail rows stay zero from static init)
__device__ __align__(16) unsigned short g_Bh[3 * 131072];   // [layer][c(1024)][k(128)] n-major
__device__ __align__(16) unsigned short g_Bl[3 * 131072];
__device__ __align__(16) unsigned short g_Ahi[(size_t)NPAD * 128];  // row-major
__device__ __align__(16) unsigned short g_Alo[(size_t)NPAD * 128];

// ---------------- f32x2 packed math ----------------
__device__ __forceinline__ u64 pk2(float lo, float hi) {
    u64 r; asm("mov.b64 %0, {%1,%2};" : "=l"(r) : "f"(lo), "f"(hi)); return r;
}
__device__ __forceinline__ void upk2(u64 v, float& lo, float& hi) {
    asm("mov.b64 {%0,%1}, %2;" : "=f"(lo), "=f"(hi) : "l"(v));
}
__device__ __forceinline__ u64 fma2(u64 a, u64 b, u64 c) {
    u64 d; asm("fma.rn.f32x2 %0, %1, %2, %3;" : "=l"(d) : "l"(a), "l"(b), "l"(c)); return d;
}
__device__ __forceinline__ u64 add2(u64 a, u64 b) {
    u64 d; asm("add.rn.f32x2 %0, %1, %2;" : "=l"(d) : "l"(a), "l"(b)); return d;
}

// ---------------- activations ----------------
__device__ __forceinline__ float softplusf_(float x) {
    return fmaxf(x, 0.f) + __logf(1.f + __expf(-fabsf(x)));
}

// gate for two nodes at once: g2A=(fA,cA), g2B=(fB,cB) in half2.
// sigmoid via tanh.approx.f16x2, exp via ex2.approx.f16x2,
// log1p(u) via degree-6 packed-f32x2 Taylor at u=0.5 (|err| <= 6.5e-5 on u in [0,1]).
__device__ __forceinline__ void gate2_(__half2 g2A, __half2 g2B, float& aA, float& aB)
{
    __half2 fAB = __halves2half2(__low2half(g2A), __low2half(g2B));
    __half2 cAB = __halves2half2(__high2half(g2A), __high2half(g2B));
    const __half2 h_half = __float2half2_rn(0.5f);
    __half2 th, u;
    __half2 harg = __hmul2(fAB, h_half);
    asm("tanh.approx.f16x2 %0, %1;" : "=r"(*(unsigned*)&th) : "r"(*(unsigned*)&harg));
    __half2 sig = __hfma2(th, h_half, h_half);
    __half2 relu = __hmax2(cAB, __float2half2_rn(0.f));
    __half2 earg = __hmul2(__habs2(cAB), __float2half2_rn(-1.44269504f));
    asm("ex2.approx.f16x2 %0, %1;" : "=r"(*(unsigned*)&u) : "r"(*(unsigned*)&earg));
    float2 uf = __half22float2(u);

    // packed log1p poly: d = u - 0.5; ln(1+u) = ln1.5 + d*(c1 + d*(c2 + ...))
    const u64 NH  = pk2(-0.5f, -0.5f);
    const u64 C6  = pk2(-0.014631916f, -0.014631916f);
    const u64 C5  = pk2( 0.026337449f,  0.026337449f);
    const u64 C4  = pk2(-0.049382716f, -0.049382716f);
    const u64 C3  = pk2( 0.098765432f,  0.098765432f);
    const u64 C2  = pk2(-0.222222222f, -0.222222222f);
    const u64 C1  = pk2( 0.666666667f,  0.666666667f);
    const u64 C0  = pk2( 0.405465108f,  0.405465108f);   // ln 1.5
    u64 d = add2(pk2(uf.x, uf.y), NH);
    u64 r = fma2(C6, d, C5);
    r = fma2(r, d, C4);
    r = fma2(r, d, C3);
    r = fma2(r, d, C2);
    r = fma2(r, d, C1);
    u64 l2 = fma2(r, d, C0);
    float lx, ly; upk2(l2, lx, ly);

    float2 rf = __half22float2(relu);
    float2 sgf = __half22float2(sig);
    aA = fmaf(sgf.x, rf.x + lx, aA);
    aB = fmaf(sgf.y, rf.y + ly, aB);
}

// ---------------- bf16 split helper ----------------
__device__ __forceinline__ void bf16split(float v, unsigned short& hs, unsigned short& ls)
{
    __nv_bfloat16 hb = __float2bfloat16(v);
    float hf = __bfloat162float(hb);
    __nv_bfloat16 lb = __float2bfloat16(v - hf);
    hs = *(unsigned short*)&hb;
    ls = *(unsigned short*)&lb;
}

// ---------------- bf16 mma / ldmatrix / cp.async helpers ----------------
__device__ __forceinline__ void mma_bf16(float* c, const unsigned* a, unsigned b0, unsigned b1)
{
    asm volatile(
        "mma.sync.aligned.m16n8k16.row.col.f32.bf16.bf16.f32 "
        "{%0,%1,%2,%3},{%4,%5,%6,%7},{%8,%9},{%0,%1,%2,%3};"
        : "+f"(c[0]), "+f"(c[1]), "+f"(c[2]), "+f"(c[3])
        : "r"(a[0]), "r"(a[1]), "r"(a[2]), "r"(a[3]), "r"(b0), "r"(b1));
}
__device__ __forceinline__ void ldsm_x4(unsigned* r, const unsigned short* p)
{
    unsigned addr = (unsigned)__cvta_generic_to_shared(p);
    asm volatile("ldmatrix.sync.aligned.m8n8.x4.shared.b16 {%0,%1,%2,%3}, [%4];"
                 : "=r"(r[0]), "=r"(r[1]), "=r"(r[2]), "=r"(r[3]) : "r"(addr));
}
__device__ __forceinline__ void cp_async16(unsigned short* s, const unsigned short* g)
{
    unsigned saddr = (unsigned)__cvta_generic_to_shared(s);
    asm volatile("cp.async.cg.shared.global [%0], [%1], 16;" :: "r"(saddr), "l"(g) : "memory");
}

// ---------------- 1: merged prep: detect + folded edge weights + bf16 B planes + embed(+split) ----------------
__global__ __launch_bounds__(256) void prep_kernel(
    const unsigned* __restrict__ p2u,
    const float* __restrict__ ae, const float* __restrict__ embW, const float* __restrict__ embB,
    const float* __restrict__ cheFW, const float* __restrict__ cheFb,
    const float* __restrict__ cheGW, const float* __restrict__ cheGb,
    const float* __restrict__ vdwFW, const float* __restrict__ vdwFb,
    const float* __restrict__ vdwGW, const float* __restrict__ vdwGb)
{
    int bid = blockIdx.x;
    int tid = threadIdx.x;
    if (bid == 0 && tid == 0) g_order = (p2u[0] > 1000000u) ? 1 : 0;

    if (bid < 126) {
        int layer = bid / 42, rem = bid % 42;
        int half = rem / 21, k = rem % 21;
        const float* fW = (half ? vdwFW : cheFW) + layer * 2560;
        const float* fb = (half ? vdwFb : cheFb) + layer * 128;
        const float* gW = (half ? vdwGW : cheGW) + (size_t)layer * 98304;
        const float* gb = (half ? vdwGb : cheGb) + layer * 256;
        float* We = g_We + (layer * 2 + half) * 5120;
        float* be = g_be + (layer * 2 + half) * 256;
        int c = tid;
        if (k < ERBF) {
            float s = 0.f;
            for (int hh = 0; hh < 128; hh++) s = fmaf(fW[k * 128 + hh], gW[(size_t)(128 + hh) * 256 + c], s);
            We[k * 256 + c] = s;
        } else {
            float s = gb[c];
            for (int hh = 0; hh < 128; hh++) s = fmaf(fb[hh], gW[(size_t)(128 + hh) * 256 + c], s);
            be[c] = s;
        }
    } else if (bid < 126 + 1536) {
        // bf16 split B planes, n-major [c][k]
        int idx = (bid - 126) * 256 + tid;             // [0, 393216)
        int layer = idx >> 17;
        int within = idx & 131071;
        int k = within >> 10;
        int c = within & 1023;
        int region = c >> 8;                           // 0 S_che, 1 T_che, 2 S_vdw, 3 T_vdw
        int cc = c & 255;
        int h = cc >> 1, p = cc & 1;                   // p=0 filt, p=1 core
        const float* gW = ((region < 2) ? cheGW : vdwGW) + (size_t)layer * 98304;
        int row = ((region & 1) ? 256 : 0) + k;
        float val = gW[(size_t)row * 256 + p * 128 + h];
        size_t o = (size_t)layer * 131072 + (size_t)c * 128 + k;
        bf16split(val, g_Bh[o], g_Bl[o]);
    } else {
        __shared__ float sW[13 * 128];
        __shared__ float sa[32 * 13];
        int h = tid & 127, grp = tid >> 7;
        int n0 = (bid - (126 + 1536)) * 32;
        for (int i = tid; i < 13 * 128; i += 256) sW[i] = embW[i];
        for (int i = tid; i < 32 * 13; i += 256) sa[i] = ae[n0 * 13 + i];
        float bb = embB[h];
        __syncthreads();
#pragma unroll
        for (int nn = 0; nn < 16; nn++) {
            int ln = grp * 16 + nn;
            float s = bb;
#pragma unroll
            for (int k = 0; k < 13; k++) s = fmaf(sa[ln * 13 + k], sW[k * 128 + h], s);
            int n = n0 + ln;
            g_nodesA[(size_t)n * 128 + h] = s;
            bf16split(s, g_Ahi[(size_t)n * 128 + h], g_Alo[(size_t)n * 128 + h]);
        }
    }
}

// ---------------- 2: edge lookup tables (Chebyshev) -> packed fp16 pairs directly ----------------
__global__ __launch_bounds__(128) void table16_kernel()
{
    int j = blockIdx.x, lh = blockIdx.y, half = lh & 1, h = threadIdx.x;
    const float* We = g_We + lh * 5120;
    float bef = g_be[lh * 256 + h];
    float bec = g_be[lh * 256 + 128 + h];
    float cut  = half ? 12.f : 8.f;
    float dmax = half ? DMAX_VDW : DMAX_CHE;
    float step = dmax / (float)(KNOT - 3);
    int j1 = (j + 1 < KNOT) ? (j + 1) : (KNOT - 1);
    float d0 = (float)j * step, d1 = (float)j1 * step;

    float x0 = d0 * (PI_F / cut), x1 = d1 * (PI_F / cut);
    float sn_0 = sinf(x0), cs_0 = cosf(x0);
    float sn_1 = sinf(x1), cs_1 = cosf(x1);
    float coef0 = (d0 < cut && d0 > 1e-6f) ? 0.5f * (cs_0 + 1.f) / d0 : 0.f;
    float coef1 = (d1 < cut && d1 > 1e-6f) ? 0.5f * (cs_1 + 1.f) / d1 : 0.f;
    float c20 = 2.f * cs_0, c21 = 2.f * cs_1;
    float sk0 = sn_0, skm0 = 0.f, sk1 = sn_1, skm1 = 0.f;
    float f0 = bef, c0 = bec, f1 = bef, c1 = bec;
#pragma unroll
    for (int k = 0; k < ERBF; k++) {
        float wf = We[k * 256 + h], wc = We[k * 256 + 128 + h];
        float r0 = sk0 * coef0, r1 = sk1 * coef1;
        f0 = fmaf(r0, wf, f0); c0 = fmaf(r0, wc, c0);
        f1 = fmaf(r1, wf, f1); c1 = fmaf(r1, wc, c1);
        float t0 = fmaf(c20, sk0, -skm0); skm0 = sk0; sk0 = t0;
        float t1 = fmaf(c21, sk1, -skm1); skm1 = sk1; sk1 = t1;
    }
    __half2 a = __floats2half2_rn(f0, c0);
    __half2 b = __floats2half2_rn(f1, c1);
    uint2 v;
    v.x = *(unsigned*)&a;
    v.y = *(unsigned*)&b;
    g_tab16[((size_t)lh * KNOT + j) * 128 + h] = v;
}

// ---------------- 3: persistent-column tensor-core ST GEMM ----------------
// grid (8, 18), 256 threads, dyn smem 147456 B, 1 CTA/SM, single wave.
__global__ __launch_bounds__(256, 1) void mma_kernel(int layer)
{
    extern __shared__ __align__(16) unsigned short smu[];
    // layout: [Bh kc0][Bh kc1][Bl kc0][Bl kc1][Abuf0: Ah|Al][Abuf1: Ah|Al], each CH shorts

    int tid = threadIdx.x;
    int lane = tid & 31, wid = tid >> 5;
    int g = lane >> 2, tg = lane & 3;
    int wm = wid & 3, wn = wid >> 2;
    int c0 = blockIdx.x * 128;
    int by = blockIdx.y;

    const unsigned short* gBh = g_Bh + (size_t)layer * 131072 + (size_t)c0 * 128;
    const unsigned short* gBl = g_Bl + (size_t)layer * 131072 + (size_t)c0 * 128;

    // prefetch B: both planes, both k-chunks (4096 uint4)
#pragma unroll
    for (int j = 0; j < 16; j++) {
        int it = tid + j * 256;
        int plane = it >> 11;
        int kc = (it >> 10) & 1;
        int r = (it >> 3) & 127;
        int pos = it & 7;
        const unsigned short* src = (plane ? gBl : gBh) + r * 128 + kc * 64 + pos * 8;
        cp_async16(smu + plane * 2 * CH + kc * CH + r * 72 + pos * 8, src);
    }
    asm volatile("cp.async.commit_group;" ::: "memory");

    auto prefA = [&](int row_blk, int kcc, int buf) {
        const unsigned short* gah = g_Ahi + (size_t)row_blk * 128 * 128;
        const unsigned short* gal = g_Alo + (size_t)row_blk * 128 * 128;
        unsigned short* dstb = smu + 4 * CH + buf * 2 * CH;
#pragma unroll
        for (int j = 0; j < 8; j++) {
            int it = tid + j * 256;
            int plane = it >> 10;
            int r = (it >> 3) & 127;
            int pos = it & 7;
            const unsigned short* src = (plane ? gal : gah) + (size_t)r * 128 + kcc * 64 + pos * 8;
            cp_async16(dstb + plane * CH + r * 72 + pos * 8, src);
        }
    };

    prefA(min(by * 9, 156), 0, 0);
    asm volatile("cp.async.commit_group;" ::: "memory");

    int mrow = lane & 7, msel = lane >> 3;
    int a_row = (msel & 1) * 8 + mrow;
    int a_col = (msel >> 1) * 8;
    int b_row = (msel >> 1) * 8 + mrow;
    int b_col = (msel & 1) * 8;

    float acc[2][8][4];
#pragma unroll
    for (int a = 0; a < 2; a++)
#pragma unroll
        for (int b = 0; b < 8; b++)
#pragma unroll
            for (int c = 0; c < 4; c++) acc[a][b][c] = 0.f;

#pragma unroll 1
    for (int s = 0; s < 18; s++) {
        int rb = s >> 1, kc = s & 1;
        if (s + 1 < 18) {
            int sn = s + 1;
            prefA(min(by * 9 + (sn >> 1), 156), sn & 1, sn & 1);
        }
        asm volatile("cp.async.commit_group;" ::: "memory");
        asm volatile("cp.async.wait_group 1;" ::: "memory");
        __syncthreads();

        const unsigned short* sAh = smu + 4 * CH + kc * 2 * CH;
        const unsigned short* sAl = sAh + CH;
        const unsigned short* sBh = smu + kc * CH;
        const unsigned short* sBl = smu + 2 * CH + kc * CH;

#pragma unroll
        for (int ks = 0; ks < 4; ks++) {
            unsigned ah[2][4], al[2][4];
#pragma unroll
            for (int mt = 0; mt < 2; mt++) {
                int off = (wm * 32 + mt * 16 + a_row) * 72 + ks * 16 + a_col;
                ldsm_x4(ah[mt], sAh + off);
                ldsm_x4(al[mt], sAl + off);
            }
#pragma unroll
            for (int nt2 = 0; nt2 < 4; nt2++) {
                int off = (wn * 64 + nt2 * 16 + b_row) * 72 + ks * 16 + b_col;
                unsigned bh4[4], bl4[4];
                ldsm_x4(bh4, sBh + off);
                ldsm_x4(bl4, sBl + off);
#pragma unroll
                for (int half = 0; half < 2; half++) {
                    int nt = nt2 * 2 + half;
                    unsigned b0h = bh4[half * 2], b1h = bh4[half * 2 + 1];
                    unsigned b0l = bl4[half * 2], b1l = bl4[half * 2 + 1];
#pragma unroll
                    for (int mt = 0; mt < 2; mt++) {
                        mma_bf16(acc[mt][nt], ah[mt], b0h, b1h);
                        mma_bf16(acc[mt][nt], al[mt], b0h, b1h);
                        mma_bf16(acc[mt][nt], ah[mt], b0l, b1l);
                    }
                }
            }
        }

        if (kc == 1) {
            int row = by * 9 + rb;
#pragma unroll
            for (int mt = 0; mt < 2; mt++) {
                int m = row * 128 + wm * 32 + mt * 16 + g;
#pragma unroll
                for (int nt = 0; nt < 8; nt++) {
                    int col = c0 + wn * 64 + nt * 8 + tg * 2;
                    __half2 v0 = __floats2half2_rn(acc[mt][nt][0], acc[mt][nt][1]);
                    __half2 v1 = __floats2half2_rn(acc[mt][nt][2], acc[mt][nt][3]);
                    if (m < NPTS)     g_STh[(size_t)m * 512 + (col >> 1)] = v0;
                    if (m + 8 < NPTS) g_STh[(size_t)(m + 8) * 512 + (col >> 1)] = v1;
                }
            }
#pragma unroll
            for (int a = 0; a < 2; a++)
#pragma unroll
                for (int b = 0; b < 8; b++)
#pragma unroll
                    for (int c = 0; c < 4; c++) acc[a][b][c] = 0.f;
        }
        __syncthreads();
    }
}

// ---------------- 4: fused gated conv — byte offsets, f16x2 gate + poly log1p, 2-node pipelines ----------------
__global__ __launch_bounds__(128) void conv_kernel(
    const float* __restrict__ che_fea, const float* __restrict__ p2f, const float* __restrict__ p3f,
    const int* __restrict__ p2i, const int* __restrict__ p3i,
    const int* __restrict__ vdw_idx, int src, int layer)
{
    const int* che_idx = g_order ? p3i : p2i;
    const float* vdw_fea = g_order ? p2f : p3f;
    const float* __restrict__ nodes = src ? g_nodesB : g_nodesA;
    float* __restrict__ nodes_out = src ? g_nodesA : g_nodesB;

    __shared__ __align__(16) uint4 s_pk[NBLK * MNBR];   // {idx_byteoff, knot_byteoff, fr_half2, 0}
    __shared__ float s_acc[NBLK * 128];

    int h = threadIdx.x;
    int n0 = blockIdx.x * NBLK;
#pragma unroll
    for (int i = 0; i < NBLK; i++) s_acc[i * 128 + h] = 0.f;

#pragma unroll 1
    for (int half = 0; half < 2; half++) {
        const char* tbb = (const char*)(g_tab16 + (size_t)(layer * 2 + half) * KNOT * 128) + h * 8;
        const float* feap = half ? vdw_fea : che_fea;
        const int* idxp = half ? vdw_idx : che_idx;
        float scale = half ? ((float)(KNOT - 3) / DMAX_VDW) : ((float)(KNOT - 3) / DMAX_CHE);
        const char* stb = (const char*)g_STh + ((half ? 384 : 128) + h) * 4;  // T region byte base
        int soff = (half ? 256 : 0) + h;                                       // S region half2 index

        __syncthreads();
        for (int i = h; i < NBLK * MNBR; i += 128) {
            float d = feap[n0 * MNBR + i];
            float u = fminf(d * scale, (float)(KNOT - 3));
            float jf = floorf(u);
            float fr = u - jf;
            __half2 frh = __float2half2_rn(fr);
            s_pk[i] = make_uint4((unsigned)idxp[n0 * MNBR + i] * 2048u,
                                 (unsigned)jf * 1024u,
                                 *(unsigned*)&frh, 0u);
        }
        __syncthreads();

#pragma unroll 1
        for (int nn = 0; nn < NBLK; nn += 2) {
            int nA = n0 + nn, nB = nA + 1;
            int iA = nn * MNBR, iB = iA + MNBR;
            __half2 svA = g_STh[(size_t)nA * 512 + soff];
            __half2 svB = g_STh[(size_t)nB * 512 + soff];

            __half2 tgA[2], tgB[2];
            uint2   tpA[2], tpB[2];
            unsigned frA[2], frB[2];
#pragma unroll
            for (int s = 0; s < 2; s++) {
                uint4 pA = s_pk[iA + s];
                uint4 pB = s_pk[iB + s];
                tgA[s] = *(const __half2*)(stb + pA.x);
                tpA[s] = *(const uint2*)(tbb + pA.y);
                frA[s] = pA.z;
                tgB[s] = *(const __half2*)(stb + pB.x);
                tpB[s] = *(const uint2*)(tbb + pB.y);
                frB[s] = pB.z;
            }

            float aA = 0.f, aB = 0.f;
#pragma unroll
            for (int m = 0; m < MNBR; m++) {
                int s = m & 1;
                __half2 tgAc = tgA[s]; uint2 tpAc = tpA[s]; unsigned frAc = frA[s];
                __half2 tgBc = tgB[s]; uint2 tpBc = tpB[s]; unsigned frBc = frB[s];
                if (m + 2 < MNBR) {
                    uint4 pA = s_pk[iA + m + 2];
                    uint4 pB = s_pk[iB + m + 2];
                    tgA[s] = *(const __half2*)(stb + pA.x);
                    tpA[s] = *(const uint2*)(tbb + pA.y);
                    frA[s] = pA.z;
                    tgB[s] = *(const __half2*)(stb + pB.x);
                    tpB[s] = *(const uint2*)(tbb + pB.y);
                    frB[s] = pB.z;
                }

                __half2 t0A = *(__half2*)&tpAc.x, t1A = *(__half2*)&tpAc.y;
                __half2 eA = __hfma2(*(__half2*)&frAc, __hsub2(t1A, t0A), t0A);
                __half2 g2A = __hadd2(__hadd2(svA, tgAc), eA);
                __half2 t0B = *(__half2*)&tpBc.x, t1B = *(__half2*)&tpBc.y;
                __half2 eB = __hfma2(*(__half2*)&frBc, __hsub2(t1B, t0B), t0B);
                __half2 g2B = __hadd2(__hadd2(svB, tgBc), eB);
                gate2_(g2A, g2B, aA, aB);
            }
            s_acc[nn * 128 + h]       += aA;
            s_acc[(nn + 1) * 128 + h] += aB;
        }
    }
#pragma unroll
    for (int nn = 0; nn < NBLK; nn++) {
        int n = n0 + nn;
        float r = nodes[(size_t)n * 128 + h] + s_acc[nn * 128 + h];
        float sp = softplusf_(r);
        nodes_out[(size_t)n * 128 + h] = sp;
        bf16split(sp, g_Ahi[(size_t)n * 128 + h], g_Alo[(size_t)n * 128 + h]);
    }
}

// ---------------- 5: pooling + MLP head ----------------
__global__ __launch_bounds__(128) void pool_kernel(
    const int* __restrict__ num_atoms,
    const float* __restrict__ fc1W, const float* __restrict__ fc1b,
    const float* __restrict__ outW, const float* __restrict__ outb,
    float* __restrict__ out, int src)
{
    const float* __restrict__ nodes = src ? g_nodesB : g_nodesA;
    __shared__ float sA[128];
    __shared__ float sB[128];
    __shared__ int sred[128];
    int b = blockIdx.x, h = threadIdx.x;

    int v = 0;
    for (int i = h; i < b; i += 128) v += num_atoms[i];
    sred[h] = v;
    __syncthreads();
    for (int off = 64; off > 0; off >>= 1) {
        if (h < off) sred[h] += sred[h + off];
        __syncthreads();
    }
    int start = sred[0];
    int cnt = num_atoms[b];

    float s = 0.f;
    for (int a = 0; a < cnt; a++) s += nodes[(size_t)(start + a) * 128 + h];
    sA[h] = softplusf_(s / (float)cnt);
    __syncthreads();
    float t = fc1b[h];
    for (int k = 0; k < 128; k++) t = fmaf(sA[k], fc1W[k * 128 + h], t);
    sB[h] = softplusf_(t) * outW[h];
    __syncthreads();
    for (int off = 64; off > 0; off >>= 1) {
        if (h < off) sB[h] += sB[h + off];
        __syncthreads();
    }
    if (h == 0) out[b] = sB[0] + outb[0];
}

// ---------------- launch ----------------
extern "C" void kernel_launch(void* const* d_in, const int* in_sizes, int n_in,
                              void* d_out, int out_size)
{
    const float* ae      = (const float*)d_in[0];
    const float* che_fea = (const float*)d_in[1];
    const void*  p2      = d_in[2];
    const void*  p3      = d_in[3];
    const int*   vdw_idx = (const int*)d_in[4];
    const int*   natoms  = (const int*)d_in[5];
    const float* embW    = (const float*)d_in[6];
    const float* embB    = (const float*)d_in[7];
    const float* cheFW   = (const float*)d_in[8];
    const float* cheFb   = (const float*)d_in[9];
    const float* cheGW   = (const float*)d_in[10];
    const float* cheGb   = (const float*)d_in[11];
    const float* vdwFW   = (const float*)d_in[12];
    const float* vdwFb   = (const float*)d_in[13];
    const float* vdwGW   = (const float*)d_in[14];
    const float* vdwGb   = (const float*)d_in[15];
    const float* fc1W    = (const float*)d_in[16];
    const float* fc1b    = (const float*)d_in[17];
    const float* outW    = (const float*)d_in[18];
    const float* outb    = (const float*)d_in[19];

    const int MMA_SMEM = 8 * CH * 2;   // 147456 B
    static int attr_set = 0;
    if (!attr_set) {
        cudaFuncSetAttribute(mma_kernel, cudaFuncAttributeMaxDynamicSharedMemorySize, MMA_SMEM);
        attr_set = 1;
    }

    prep_kernel<<<126 + 1536 + 625, 256>>>((const unsigned*)p2, ae, embW, embB,
                                           cheFW, cheFb, cheGW, cheGb,
                                           vdwFW, vdwFb, vdwGW, vdwGb);
    table16_kernel<<<dim3(KNOT, 6), 128>>>();

    int src = 0;
    for (int i = 0; i < 3; i++) {
        mma_kernel<<<dim3(8, 18), 256, MMA_SMEM>>>(i);
        conv_kernel<<<NPTS / NBLK, 128>>>(che_fea, (const float*)p2, (const float*)p3,
                                          (const int*)p2, (const int*)p3, vdw_idx, src, i);
        src ^= 1;
    }
    pool_kernel<<<BCRY, 128>>>(natoms, fc1W, fc1b, outW, outb, (float*)d_out, src);
}

// round 17
// speedup vs baseline: 1.0685x; 1.0685x over previous
#include <cuda_runtime.h>
#include <cuda_fp16.h>
#include <cuda_bf16.h>
#include <cstdint>

// ---------------- problem constants ----------------
#define NPTS 20000
#define NPAD 20096          // 157*128
#define MNBR 20
#define ERBF 20
#define HDIM 128
#define BCRY 200
#define NBLK 8
#define PI_F 3.14159265358979f
#define KNOT 4096
#define DMAX_CHE 8.81f
#define DMAX_VDW 13.21f
#define CH (128 * 72)       // shorts per plane per k-chunk

typedef unsigned long long u64;

// ---------------- device scratch ----------------
__device__ int   g_order;
__device__ float g_nodesA[NPTS * HDIM];
__device__ float g_nodesB[NPTS * HDIM];
__device__ __half2 g_STh[(size_t)NPTS * 512];            // [S_che|T_che|S_vdw|T_vdw] x 128 half2 (filt,core)
__device__ float g_We[3 * 2 * ERBF * 256];
__device__ float g_be[3 * 2 * 256];
__device__ uint2 g_tab16[(size_t)3 * 2 * KNOT * 128];    // packed fp16: {f_j,c_j,f_j+1,c_j+1} per (j,h)
// bf16 split operands for tensor-core GEMM (tail rows stay zero from static init)
__device__ __align__(16) unsigned short g_Bh[3 * 131072];   // [layer][c(1024)][k(128)] n-major
__device__ __align__(16) unsigned short g_Bl[3 * 131072];
__device__ __align__(16) unsigned short g_Ahi[(size_t)NPAD * 128];  // row-major
__device__ __align__(16) unsigned short g_Alo[(size_t)NPAD * 128];

// ---------------- activations ----------------
__device__ __forceinline__ float softplusf_(float x) {
    return fmaxf(x, 0.f) + __logf(1.f + __expf(-fabsf(x)));
}

// gate for two nodes at once (r15-measured version): tanh.f16x2 sigmoid, ex2.f16x2, lg2 f32.
__device__ __forceinline__ void gate2_(__half2 g2A, __half2 g2B, float& aA, float& aB)
{
    __half2 fAB = __halves2half2(__low2half(g2A), __low2half(g2B));
    __half2 cAB = __halves2half2(__high2half(g2A), __high2half(g2B));
    const __half2 h_half = __float2half2_rn(0.5f);
    __half2 th, u;
    __half2 harg = __hmul2(fAB, h_half);
    asm("tanh.approx.f16x2 %0, %1;" : "=r"(*(unsigned*)&th) : "r"(*(unsigned*)&harg));
    __half2 sig = __hfma2(th, h_half, h_half);
    __half2 relu = __hmax2(cAB, __float2half2_rn(0.f));
    __half2 earg = __hmul2(__habs2(cAB), __float2half2_rn(-1.44269504f));
    asm("ex2.approx.f16x2 %0, %1;" : "=r"(*(unsigned*)&u) : "r"(*(unsigned*)&earg));
    float2 uf = __half22float2(u);
    float2 rf = __half22float2(relu);
    float2 sgf = __half22float2(sig);
    float lx = __logf(1.f + uf.x);
    float ly = __logf(1.f + uf.y);
    aA = fmaf(sgf.x, rf.x + lx, aA);
    aB = fmaf(sgf.y, rf.y + ly, aB);
}

// ---------------- bf16 split helper ----------------
__device__ __forceinline__ void bf16split(float v, unsigned short& hs, unsigned short& ls)
{
    __nv_bfloat16 hb = __float2bfloat16(v);
    float hf = __bfloat162float(hb);
    __nv_bfloat16 lb = __float2bfloat16(v - hf);
    hs = *(unsigned short*)&hb;
    ls = *(unsigned short*)&lb;
}

// ---------------- bf16 mma / ldmatrix / cp.async helpers ----------------
__device__ __forceinline__ void mma_bf16(float* c, const unsigned* a, unsigned b0, unsigned b1)
{
    asm volatile(
        "mma.sync.aligned.m16n8k16.row.col.f32.bf16.bf16.f32 "
        "{%0,%1,%2,%3},{%4,%5,%6,%7},{%8,%9},{%0,%1,%2,%3};"
        : "+f"(c[0]), "+f"(c[1]), "+f"(c[2]), "+f"(c[3])
        : "r"(a[0]), "r"(a[1]), "r"(a[2]), "r"(a[3]), "r"(b0), "r"(b1));
}
__device__ __forceinline__ void ldsm_x4(unsigned* r, const unsigned short* p)
{
    unsigned addr = (unsigned)__cvta_generic_to_shared(p);
    asm volatile("ldmatrix.sync.aligned.m8n8.x4.shared.b16 {%0,%1,%2,%3}, [%4];"
                 : "=r"(r[0]), "=r"(r[1]), "=r"(r[2]), "=r"(r[3]) : "r"(addr));
}
__device__ __forceinline__ void cp_async16(unsigned short* s, const unsigned short* g)
{
    unsigned saddr = (unsigned)__cvta_generic_to_shared(s);
    asm volatile("cp.async.cg.shared.global [%0], [%1], 16;" :: "r"(saddr), "l"(g) : "memory");
}

// ---------------- 1: merged prep ----------------
__global__ __launch_bounds__(256) void prep_kernel(
    const unsigned* __restrict__ p2u,
    const float* __restrict__ ae, const float* __restrict__ embW, const float* __restrict__ embB,
    const float* __restrict__ cheFW, const float* __restrict__ cheFb,
    const float* __restrict__ cheGW, const float* __restrict__ cheGb,
    const float* __restrict__ vdwFW, const float* __restrict__ vdwFb,
    const float* __restrict__ vdwGW, const float* __restrict__ vdwGb)
{
    int bid = blockIdx.x;
    int tid = threadIdx.x;
    if (bid == 0 && tid == 0) g_order = (p2u[0] > 1000000u) ? 1 : 0;

    if (bid < 126) {
        int layer = bid / 42, rem = bid % 42;
        int half = rem / 21, k = rem % 21;
        const float* fW = (half ? vdwFW : cheFW) + layer * 2560;
        const float* fb = (half ? vdwFb : cheFb) + layer * 128;
        const float* gW = (half ? vdwGW : cheGW) + (size_t)layer * 98304;
        const float* gb = (half ? vdwGb : cheGb) + layer * 256;
        float* We = g_We + (layer * 2 + half) * 5120;
        float* be = g_be + (layer * 2 + half) * 256;
        int c = tid;
        if (k < ERBF) {
            float s = 0.f;
            for (int hh = 0; hh < 128; hh++) s = fmaf(fW[k * 128 + hh], gW[(size_t)(128 + hh) * 256 + c], s);
            We[k * 256 + c] = s;
        } else {
            float s = gb[c];
            for (int hh = 0; hh < 128; hh++) s = fmaf(fb[hh], gW[(size_t)(128 + hh) * 256 + c], s);
            be[c] = s;
        }
    } else if (bid < 126 + 1536) {
        int idx = (bid - 126) * 256 + tid;
        int layer = idx >> 17;
        int within = idx & 131071;
        int k = within >> 10;
        int c = within & 1023;
        int region = c >> 8;
        int cc = c & 255;
        int h = cc >> 1, p = cc & 1;
        const float* gW = ((region < 2) ? cheGW : vdwGW) + (size_t)layer * 98304;
        int row = ((region & 1) ? 256 : 0) + k;
        float val = gW[(size_t)row * 256 + p * 128 + h];
        size_t o = (size_t)layer * 131072 + (size_t)c * 128 + k;
        bf16split(val, g_Bh[o], g_Bl[o]);
    } else {
        __shared__ float sW[13 * 128];
        __shared__ float sa[32 * 13];
        int h = tid & 127, grp = tid >> 7;
        int n0 = (bid - (126 + 1536)) * 32;
        for (int i = tid; i < 13 * 128; i += 256) sW[i] = embW[i];
        for (int i = tid; i < 32 * 13; i += 256) sa[i] = ae[n0 * 13 + i];
        float bb = embB[h];
        __syncthreads();
#pragma unroll
        for (int nn = 0; nn < 16; nn++) {
            int ln = grp * 16 + nn;
            float s = bb;
#pragma unroll
            for (int k = 0; k < 13; k++) s = fmaf(sa[ln * 13 + k], sW[k * 128 + h], s);
            int n = n0 + ln;
            g_nodesA[(size_t)n * 128 + h] = s;
            bf16split(s, g_Ahi[(size_t)n * 128 + h], g_Alo[(size_t)n * 128 + h]);
        }
    }
}

// ---------------- 2: edge lookup tables -> packed fp16 ----------------
__global__ __launch_bounds__(128) void table16_kernel()
{
    int j = blockIdx.x, lh = blockIdx.y, half = lh & 1, h = threadIdx.x;
    const float* We = g_We + lh * 5120;
    float bef = g_be[lh * 256 + h];
    float bec = g_be[lh * 256 + 128 + h];
    float cut  = half ? 12.f : 8.f;
    float dmax = half ? DMAX_VDW : DMAX_CHE;
    float step = dmax / (float)(KNOT - 3);
    int j1 = (j + 1 < KNOT) ? (j + 1) : (KNOT - 1);
    float d0 = (float)j * step, d1 = (float)j1 * step;

    float x0 = d0 * (PI_F / cut), x1 = d1 * (PI_F / cut);
    float sn_0 = sinf(x0), cs_0 = cosf(x0);
    float sn_1 = sinf(x1), cs_1 = cosf(x1);
    float coef0 = (d0 < cut && d0 > 1e-6f) ? 0.5f * (cs_0 + 1.f) / d0 : 0.f;
    float coef1 = (d1 < cut && d1 > 1e-6f) ? 0.5f * (cs_1 + 1.f) / d1 : 0.f;
    float c20 = 2.f * cs_0, c21 = 2.f * cs_1;
    float sk0 = sn_0, skm0 = 0.f, sk1 = sn_1, skm1 = 0.f;
    float f0 = bef, c0 = bec, f1 = bef, c1 = bec;
#pragma unroll
    for (int k = 0; k < ERBF; k++) {
        float wf = We[k * 256 + h], wc = We[k * 256 + 128 + h];
        float r0 = sk0 * coef0, r1 = sk1 * coef1;
        f0 = fmaf(r0, wf, f0); c0 = fmaf(r0, wc, c0);
        f1 = fmaf(r1, wf, f1); c1 = fmaf(r1, wc, c1);
        float t0 = fmaf(c20, sk0, -skm0); skm0 = sk0; sk0 = t0;
        float t1 = fmaf(c21, sk1, -skm1); skm1 = sk1; sk1 = t1;
    }
    __half2 a = __floats2half2_rn(f0, c0);
    __half2 b = __floats2half2_rn(f1, c1);
    uint2 v;
    v.x = *(unsigned*)&a;
    v.y = *(unsigned*)&b;
    g_tab16[((size_t)lh * KNOT + j) * 128 + h] = v;
}

// ---------------- 3: persistent-column tensor-core ST GEMM (r15-measured) ----------------
__global__ __launch_bounds__(256, 1) void mma_kernel(int layer)
{
    extern __shared__ __align__(16) unsigned short smu[];

    int tid = threadIdx.x;
    int lane = tid & 31, wid = tid >> 5;
    int g = lane >> 2, tg = lane & 3;
    int wm = wid & 3, wn = wid >> 2;
    int c0 = blockIdx.x * 128;
    int by = blockIdx.y;

    const unsigned short* gBh = g_Bh + (size_t)layer * 131072 + (size_t)c0 * 128;
    const unsigned short* gBl = g_Bl + (size_t)layer * 131072 + (size_t)c0 * 128;

#pragma unroll
    for (int j = 0; j < 16; j++) {
        int it = tid + j * 256;
        int plane = it >> 11;
        int kc = (it >> 10) & 1;
        int r = (it >> 3) & 127;
        int pos = it & 7;
        const unsigned short* src = (plane ? gBl : gBh) + r * 128 + kc * 64 + pos * 8;
        cp_async16(smu + plane * 2 * CH + kc * CH + r * 72 + pos * 8, src);
    }
    asm volatile("cp.async.commit_group;" ::: "memory");

    auto prefA = [&](int row_blk, int kcc, int buf) {
        const unsigned short* gah = g_Ahi + (size_t)row_blk * 128 * 128;
        const unsigned short* gal = g_Alo + (size_t)row_blk * 128 * 128;
        unsigned short* dstb = smu + 4 * CH + buf * 2 * CH;
#pragma unroll
        for (int j = 0; j < 8; j++) {
            int it = tid + j * 256;
            int plane = it >> 10;
            int r = (it >> 3) & 127;
            int pos = it & 7;
            const unsigned short* src = (plane ? gal : gah) + (size_t)r * 128 + kcc * 64 + pos * 8;
            cp_async16(dstb + plane * CH + r * 72 + pos * 8, src);
        }
    };

    prefA(min(by * 9, 156), 0, 0);
    asm volatile("cp.async.commit_group;" ::: "memory");

    int mrow = lane & 7, msel = lane >> 3;
    int a_row = (msel & 1) * 8 + mrow;
    int a_col = (msel >> 1) * 8;
    int b_row = (msel >> 1) * 8 + mrow;
    int b_col = (msel & 1) * 8;

    float acc[2][8][4];
#pragma unroll
    for (int a = 0; a < 2; a++)
#pragma unroll
        for (int b = 0; b < 8; b++)
#pragma unroll
            for (int c = 0; c < 4; c++) acc[a][b][c] = 0.f;

#pragma unroll 1
    for (int s = 0; s < 18; s++) {
        int rb = s >> 1, kc = s & 1;
        if (s + 1 < 18) {
            int sn = s + 1;
            prefA(min(by * 9 + (sn >> 1), 156), sn & 1, sn & 1);
        }
        asm volatile("cp.async.commit_group;" ::: "memory");
        asm volatile("cp.async.wait_group 1;" ::: "memory");
        __syncthreads();

        const unsigned short* sAh = smu + 4 * CH + kc * 2 * CH;
        const unsigned short* sAl = sAh + CH;
        const unsigned short* sBh = smu + kc * CH;
        const unsigned short* sBl = smu + 2 * CH + kc * CH;

#pragma unroll
        for (int ks = 0; ks < 4; ks++) {
            unsigned ah[2][4], al[2][4];
#pragma unroll
            for (int mt = 0; mt < 2; mt++) {
                int off = (wm * 32 + mt * 16 + a_row) * 72 + ks * 16 + a_col;
                ldsm_x4(ah[mt], sAh + off);
                ldsm_x4(al[mt], sAl + off);
            }
#pragma unroll
            for (int nt2 = 0; nt2 < 4; nt2++) {
                int off = (wn * 64 + nt2 * 16 + b_row) * 72 + ks * 16 + b_col;
                unsigned bh4[4], bl4[4];
                ldsm_x4(bh4, sBh + off);
                ldsm_x4(bl4, sBl + off);
#pragma unroll
                for (int half = 0; half < 2; half++) {
                    int nt = nt2 * 2 + half;
                    unsigned b0h = bh4[half * 2], b1h = bh4[half * 2 + 1];
                    unsigned b0l = bl4[half * 2], b1l = bl4[half * 2 + 1];
#pragma unroll
                    for (int mt = 0; mt < 2; mt++) {
                        mma_bf16(acc[mt][nt], ah[mt], b0h, b1h);
                        mma_bf16(acc[mt][nt], al[mt], b0h, b1h);
                        mma_bf16(acc[mt][nt], ah[mt], b0l, b1l);
                    }
                }
            }
        }

        if (kc == 1) {
            int row = by * 9 + rb;
#pragma unroll
            for (int mt = 0; mt < 2; mt++) {
                int m = row * 128 + wm * 32 + mt * 16 + g;
#pragma unroll
                for (int nt = 0; nt < 8; nt++) {
                    int col = c0 + wn * 64 + nt * 8 + tg * 2;
                    __half2 v0 = __floats2half2_rn(acc[mt][nt][0], acc[mt][nt][1]);
                    __half2 v1 = __floats2half2_rn(acc[mt][nt][2], acc[mt][nt][3]);
                    if (m < NPTS)     g_STh[(size_t)m * 512 + (col >> 1)] = v0;
                    if (m + 8 < NPTS) g_STh[(size_t)(m + 8) * 512 + (col >> 1)] = v1;
                }
            }
#pragma unroll
            for (int a = 0; a < 2; a++)
#pragma unroll
                for (int b = 0; b < 8; b++)
#pragma unroll
                    for (int c = 0; c < 4; c++) acc[a][b][c] = 0.f;
        }
        __syncthreads();
    }
}

// ---------------- 4: fused gated conv — depth-4 pipeline, f16x2 gate, 2-node interleave ----------------
__global__ __launch_bounds__(128) void conv_kernel(
    const float* __restrict__ che_fea, const float* __restrict__ p2f, const float* __restrict__ p3f,
    const int* __restrict__ p2i, const int* __restrict__ p3i,
    const int* __restrict__ vdw_idx, int src, int layer)
{
    const int* che_idx = g_order ? p3i : p2i;
    const float* vdw_fea = g_order ? p2f : p3f;
    const float* __restrict__ nodes = src ? g_nodesB : g_nodesA;
    float* __restrict__ nodes_out = src ? g_nodesA : g_nodesB;

    __shared__ __align__(16) uint4 s_pk[NBLK * MNBR];   // {idx_byteoff, knot_byteoff, fr_half2, 0}
    __shared__ float s_acc[NBLK * 128];

    int h = threadIdx.x;
    int n0 = blockIdx.x * NBLK;
#pragma unroll
    for (int i = 0; i < NBLK; i++) s_acc[i * 128 + h] = 0.f;

#pragma unroll 1
    for (int half = 0; half < 2; half++) {
        const char* tbb = (const char*)(g_tab16 + (size_t)(layer * 2 + half) * KNOT * 128) + h * 8;
        const float* feap = half ? vdw_fea : che_fea;
        const int* idxp = half ? vdw_idx : che_idx;
        float scale = half ? ((float)(KNOT - 3) / DMAX_VDW) : ((float)(KNOT - 3) / DMAX_CHE);
        const char* stb = (const char*)g_STh + ((half ? 384 : 128) + h) * 4;  // T region byte base
        int soff = (half ? 256 : 0) + h;                                       // S region half2 index

        __syncthreads();
        for (int i = h; i < NBLK * MNBR; i += 128) {
            float d = feap[n0 * MNBR + i];
            float u = fminf(d * scale, (float)(KNOT - 3));
            float jf = floorf(u);
            float fr = u - jf;
            __half2 frh = __float2half2_rn(fr);
            s_pk[i] = make_uint4((unsigned)idxp[n0 * MNBR + i] * 2048u,
                                 (unsigned)jf * 1024u,
                                 *(unsigned*)&frh, 0u);
        }
        __syncthreads();

#pragma unroll 1
        for (int nn = 0; nn < NBLK; nn += 2) {
            int nA = n0 + nn, nB = nA + 1;
            int iA = nn * MNBR, iB = iA + MNBR;
            __half2 svA = g_STh[(size_t)nA * 512 + soff];
            __half2 svB = g_STh[(size_t)nB * 512 + soff];

            // depth-4 software pipeline per node
            __half2 tgA[4], tgB[4];
            uint2   tpA[4], tpB[4];
            unsigned frA[4], frB[4];
#pragma unroll
            for (int s = 0; s < 4; s++) {
                uint4 pA = s_pk[iA + s];
                uint4 pB = s_pk[iB + s];
                tgA[s] = *(const __half2*)(stb + pA.x);
                tpA[s] = *(const uint2*)(tbb + pA.y);
                frA[s] = pA.z;
                tgB[s] = *(const __half2*)(stb + pB.x);
                tpB[s] = *(const uint2*)(tbb + pB.y);
                frB[s] = pB.z;
            }

            float aA = 0.f, aB = 0.f;
#pragma unroll
            for (int m = 0; m < MNBR; m++) {
                int s = m & 3;
                __half2 tgAc = tgA[s]; uint2 tpAc = tpA[s]; unsigned frAc = frA[s];
                __half2 tgBc = tgB[s]; uint2 tpBc = tpB[s]; unsigned frBc = frB[s];
                if (m + 4 < MNBR) {
                    uint4 pA = s_pk[iA + m + 4];
                    uint4 pB = s_pk[iB + m + 4];
                    tgA[s] = *(const __half2*)(stb + pA.x);
                    tpA[s] = *(const uint2*)(tbb + pA.y);
                    frA[s] = pA.z;
                    tgB[s] = *(const __half2*)(stb + pB.x);
                    tpB[s] = *(const uint2*)(tbb + pB.y);
                    frB[s] = pB.z;
                }

                __half2 t0A = *(__half2*)&tpAc.x, t1A = *(__half2*)&tpAc.y;
                __half2 eA = __hfma2(*(__half2*)&frAc, __hsub2(t1A, t0A), t0A);
                __half2 g2A = __hadd2(__hadd2(svA, tgAc), eA);
                __half2 t0B = *(__half2*)&tpBc.x, t1B = *(__half2*)&tpBc.y;
                __half2 eB = __hfma2(*(__half2*)&frBc, __hsub2(t1B, t0B), t0B);
                __half2 g2B = __hadd2(__hadd2(svB, tgBc), eB);
                gate2_(g2A, g2B, aA, aB);
            }
            s_acc[nn * 128 + h]       += aA;
            s_acc[(nn + 1) * 128 + h] += aB;
        }
    }
#pragma unroll
    for (int nn = 0; nn < NBLK; nn++) {
        int n = n0 + nn;
        float r = nodes[(size_t)n * 128 + h] + s_acc[nn * 128 + h];
        float sp = softplusf_(r);
        nodes_out[(size_t)n * 128 + h] = sp;
        bf16split(sp, g_Ahi[(size_t)n * 128 + h], g_Alo[(size_t)n * 128 + h]);
    }
}

// ---------------- 5: pooling + MLP head ----------------
__global__ __launch_bounds__(128) void pool_kernel(
    const int* __restrict__ num_atoms,
    const float* __restrict__ fc1W, const float* __restrict__ fc1b,
    const float* __restrict__ outW, const float* __restrict__ outb,
    float* __restrict__ out, int src)
{
    const float* __restrict__ nodes = src ? g_nodesB : g_nodesA;
    __shared__ float sA[128];
    __shared__ float sB[128];
    __shared__ int sred[128];
    int b = blockIdx.x, h = threadIdx.x;

    int v = 0;
    for (int i = h; i < b; i += 128) v += num_atoms[i];
    sred[h] = v;
    __syncthreads();
    for (int off = 64; off > 0; off >>= 1) {
        if (h < off) sred[h] += sred[h + off];
        __syncthreads();
    }
    int start = sred[0];
    int cnt = num_atoms[b];

    float s = 0.f;
    for (int a = 0; a < cnt; a++) s += nodes[(size_t)(start + a) * 128 + h];
    sA[h] = softplusf_(s / (float)cnt);
    __syncthreads();
    float t = fc1b[h];
    for (int k = 0; k < 128; k++) t = fmaf(sA[k], fc1W[k * 128 + h], t);
    sB[h] = softplusf_(t) * outW[h];
    __syncthreads();
    for (int off = 64; off > 0; off >>= 1) {
        if (h < off) sB[h] += sB[h + off];
        __syncthreads();
    }
    if (h == 0) out[b] = sB[0] + outb[0];
}

// ---------------- launch ----------------
extern "C" void kernel_launch(void* const* d_in, const int* in_sizes, int n_in,
                              void* d_out, int out_size)
{
    const float* ae      = (const float*)d_in[0];
    const float* che_fea = (const float*)d_in[1];
    const void*  p2      = d_in[2];
    const void*  p3      = d_in[3];
    const int*   vdw_idx = (const int*)d_in[4];
    const int*   natoms  = (const int*)d_in[5];
    const float* embW    = (const float*)d_in[6];
    const float* embB    = (const float*)d_in[7];
    const float* cheFW   = (const float*)d_in[8];
    const float* cheFb   = (const float*)d_in[9];
    const float* cheGW   = (const float*)d_in[10];
    const float* cheGb   = (const float*)d_in[11];
    const float* vdwFW   = (const float*)d_in[12];
    const float* vdwFb   = (const float*)d_in[13];
    const float* vdwGW   = (const float*)d_in[14];
    const float* vdwGb   = (const float*)d_in[15];
    const float* fc1W    = (const float*)d_in[16];
    const float* fc1b    = (const float*)d_in[17];
    const float* outW    = (const float*)d_in[18];
    const float* outb    = (const float*)d_in[19];

    const int MMA_SMEM = 8 * CH * 2;   // 147456 B
    static int attr_set = 0;
    if (!attr_set) {
        cudaFuncSetAttribute(mma_kernel, cudaFuncAttributeMaxDynamicSharedMemorySize, MMA_SMEM);
        attr_set = 1;
    }

    prep_kernel<<<126 + 1536 + 625, 256>>>((const unsigned*)p2, ae, embW, embB,
                                           cheFW, cheFb, cheGW, cheGb,
                                           vdwFW, vdwFb, vdwGW, vdwGb);
    table16_kernel<<<dim3(KNOT, 6), 128>>>();

    int src = 0;
    for (int i = 0; i < 3; i++) {
        mma_kernel<<<dim3(8, 18), 256, MMA_SMEM>>>(i);
        conv_kernel<<<NPTS / NBLK, 128>>>(che_fea, (const float*)p2, (const float*)p3,
                                          (const int*)p2, (const int*)p3, vdw_idx, src, i);
        src ^= 1;
    }
    pool_kernel<<<BCRY, 128>>>(natoms, fc1W, fc1b, outW, outb, (float*)d_out, src);
}